// round 4
// baseline (speedup 1.0000x reference)
#include <cuda_runtime.h>
#include <cstdint>

#define N_USERS    50000
#define N_ENTITIES 150000
#define N_NODES    200000
#define N_EDGES    3200000
#define BATCH      4096

typedef unsigned long long ull;

// ---------------- scratch (device globals; no allocation allowed) ----------
__device__ __align__(16) float g_hneigh[(size_t)N_NODES * 64];
__device__ __align__(16) float g_h1[(size_t)N_NODES * 64];
__device__ __align__(16) float g_h2[(size_t)N_NODES * 32];
__device__ __align__(16) int   g_count[N_NODES];
__device__ __align__(16) int   g_rowstart[N_NODES + 4];
__device__ __align__(16) int   g_cursor[N_NODES + 4];
__device__ __align__(16) int2  g_srt[N_EDGES];      // {neighbor, value-bits} sorted by target

__device__ __forceinline__ const float* feat0_row(const float* uw, const float* ew, int n) {
    return (n < N_USERS) ? (uw + (size_t)n * 64) : (ew + (size_t)(n - N_USERS) * 64);
}

__device__ __forceinline__ void ffma2(ull& d, ull a, ull b) {
    asm("fma.rn.f32x2 %0, %1, %2, %0;" : "+l"(d) : "l"(a), "l"(b));
}

// ---------------- CSR build ------------------------------------------------
__global__ void __launch_bounds__(256) k_zero_counts() {
    int i = blockIdx.x * 256 + threadIdx.x;           // int4 index
    if (i < N_NODES / 4) ((int4*)g_count)[i] = make_int4(0, 0, 0, 0);
}

__global__ void __launch_bounds__(256) k_count(const int* __restrict__ target) {
    int e = blockIdx.x * 256 + threadIdx.x;           // grid exact: 3.2M/256
    atomicAdd(&g_count[target[e]], 1);                // RED.ADD, no return
}

// Single-block scan; int4 loads (MLP ~49/thread) in both passes.
__global__ void __launch_bounds__(1024) k_scan() {
    const int CH = 196;                               // 1024*196 >= N_NODES, 196%4==0
    __shared__ int sa[1024], sb[1024];
    int t = threadIdx.x;
    int beg = t * CH;
    int end = beg + CH; if (end > N_NODES) end = N_NODES;   // tail is int4-aligned (80)
    int sum = 0;
    #pragma unroll 7
    for (int i4 = 0; i4 < CH / 4; i4++) {
        int idx = beg + i4 * 4;
        if (idx < end) {
            int4 v = ((const int4*)g_count)[idx >> 2];
            sum += v.x + v.y + v.z + v.w;
        }
    }
    sa[t] = sum;
    __syncthreads();
    int* src = sa; int* dst = sb;
    for (int off = 1; off < 1024; off <<= 1) {
        dst[t] = (t >= off) ? src[t] + src[t - off] : src[t];
        __syncthreads();
        int* tmp = src; src = dst; dst = tmp;
    }
    int run = (t > 0) ? src[t - 1] : 0;               // exclusive prefix
    #pragma unroll 7
    for (int i4 = 0; i4 < CH / 4; i4++) {
        int idx = beg + i4 * 4;
        if (idx < end) {
            int4 v = ((const int4*)g_count)[idx >> 2];
            int4 rs;
            rs.x = run;
            rs.y = rs.x + v.x;
            rs.z = rs.y + v.y;
            rs.w = rs.z + v.z;
            run  = rs.w + v.w;
            ((int4*)g_rowstart)[idx >> 2] = rs;
            ((int4*)g_cursor)[idx >> 2]   = rs;
        }
    }
    if (t == 1023) g_rowstart[N_NODES] = N_EDGES;
}

__global__ void __launch_bounds__(256) k_scatter(const int* __restrict__ target,
                                                const int* __restrict__ neighbor,
                                                const float* __restrict__ values) {
    int e = blockIdx.x * 256 + threadIdx.x;           // grid exact
    int t = target[e];
    int pos = atomicAdd(&g_cursor[t], 1);
    g_srt[pos] = make_int2(neighbor[e], __float_as_int(values[e]));
}

// ---------------- CSR gather: h_neigh[n] = sum_e feat[nb_e]*v_e -----------
// One warp per node: 16 lanes = float4 chunks, halves x unroll-2 = 4 edges
// (and 4 independent 256B feature loads) in flight per warp.
template <int LAYER>
__global__ void __launch_bounds__(256) k_gather(const float* __restrict__ uw,
                                                const float* __restrict__ ew) {
    int n = (blockIdx.x * 256 + threadIdx.x) >> 5;    // grid exact: 25000*8 warps
    int lane = threadIdx.x & 31;
    int c = lane & 15, half = lane >> 4;
    int base = g_rowstart[n];
    int end  = g_rowstart[n + 1];
    float4 acc0 = make_float4(0.f, 0.f, 0.f, 0.f);
    float4 acc1 = acc0;
    int i = base + half;
    for (; i + 2 < end; i += 4) {
        int2 e0 = g_srt[i];
        int2 e1 = g_srt[i + 2];
        const float* s0 = (LAYER == 1) ? feat0_row(uw, ew, e0.x) : (g_h1 + (size_t)e0.x * 64);
        const float* s1 = (LAYER == 1) ? feat0_row(uw, ew, e1.x) : (g_h1 + (size_t)e1.x * 64);
        float4 f0 = *(const float4*)(s0 + c * 4);
        float4 f1 = *(const float4*)(s1 + c * 4);
        float v0 = __int_as_float(e0.y);
        float v1 = __int_as_float(e1.y);
        acc0.x = fmaf(f0.x, v0, acc0.x); acc0.y = fmaf(f0.y, v0, acc0.y);
        acc0.z = fmaf(f0.z, v0, acc0.z); acc0.w = fmaf(f0.w, v0, acc0.w);
        acc1.x = fmaf(f1.x, v1, acc1.x); acc1.y = fmaf(f1.y, v1, acc1.y);
        acc1.z = fmaf(f1.z, v1, acc1.z); acc1.w = fmaf(f1.w, v1, acc1.w);
    }
    if (i < end) {
        int2 e0 = g_srt[i];
        const float* s0 = (LAYER == 1) ? feat0_row(uw, ew, e0.x) : (g_h1 + (size_t)e0.x * 64);
        float4 f0 = *(const float4*)(s0 + c * 4);
        float v0 = __int_as_float(e0.y);
        acc0.x = fmaf(f0.x, v0, acc0.x); acc0.y = fmaf(f0.y, v0, acc0.y);
        acc0.z = fmaf(f0.z, v0, acc0.z); acc0.w = fmaf(f0.w, v0, acc0.w);
    }
    acc0.x += acc1.x; acc0.y += acc1.y; acc0.z += acc1.z; acc0.w += acc1.w;
    acc0.x += __shfl_xor_sync(0xffffffffu, acc0.x, 16);
    acc0.y += __shfl_xor_sync(0xffffffffu, acc0.y, 16);
    acc0.z += __shfl_xor_sync(0xffffffffu, acc0.z, 16);
    acc0.w += __shfl_xor_sync(0xffffffffu, acc0.w, 16);
    if (half == 0)
        *(float4*)(g_hneigh + (size_t)n * 64 + c * 4) = acc0;
}

// ---------------- dense layer as register-tiled GEMM -----------------------
// out = leakyrelu( [s|p] @ [W1;W2] + b1 + b2 ), then row-l2norm.
// K = 128 (s: k 0..63, p: k 64..127), processed in 4 chunks of 32.
// LAYER=1: NOUT=64, TM=64.  LAYER=2: NOUT=32, TM=128.
template <int LAYER>
__global__ void __launch_bounds__(256) k_dense(const float* __restrict__ uw,
                                               const float* __restrict__ ew,
                                               const float* __restrict__ W1,
                                               const float* __restrict__ b1,
                                               const float* __restrict__ W2,
                                               const float* __restrict__ b2) {
    constexpr int NOUT = (LAYER == 1) ? 64 : 32;
    constexpr int CQ   = NOUT / 4;          // 16 / 8
    constexpr int TM   = (256 / CQ) * 4;    // 64 / 128

    __shared__ __align__(16) float2 As2[TM][16];     // [node][k-pair] per chunk
    __shared__ __align__(16) float2 Bs2[16][NOUT];   // [k-pair][col]

    int tid = threadIdx.x;
    int r = tid / CQ;       // node quad
    int c = tid % CQ;       // col within group
    int blockBase = blockIdx.x * TM;

    float bsum[4];
    #pragma unroll
    for (int jj = 0; jj < 4; jj++) {
        int j = c + jj * CQ;
        bsum[jj] = b1[j] + b2[j];
    }

    ull acc[4][4];
    #pragma unroll
    for (int i = 0; i < 4; i++)
        #pragma unroll
        for (int jj = 0; jj < 4; jj++) acc[i][jj] = 0ull;

    for (int kk = 0; kk < 4; kk++) {
        int base_col = (kk & 1) * 32;
        bool isP = (kk >= 2);
        for (int idx = tid; idx < TM * 8; idx += 256) {     // float4 granularity
            int m  = idx >> 3;
            int q4 = idx & 7;
            int node = blockBase + m;
            float4 fv = make_float4(0.f, 0.f, 0.f, 0.f);
            float4 gv = fv;
            if (node < N_NODES) {
                const float* fr = (LAYER == 1) ? feat0_row(uw, ew, node)
                                               : (g_h1 + (size_t)node * 64);
                fv = *(const float4*)(fr + base_col + q4 * 4);
                gv = *(const float4*)(g_hneigh + (size_t)node * 64 + base_col + q4 * 4);
            }
            float4 a;
            if (isP) { a.x = fv.x * gv.x; a.y = fv.y * gv.y; a.z = fv.z * gv.z; a.w = fv.w * gv.w; }
            else     { a.x = fv.x + gv.x; a.y = fv.y + gv.y; a.z = fv.z + gv.z; a.w = fv.w + gv.w; }
            As2[m][q4 * 2]     = make_float2(a.x, a.y);
            As2[m][q4 * 2 + 1] = make_float2(a.z, a.w);
        }
        for (int idx = tid; idx < 16 * NOUT; idx += 256) {
            int kp = idx / NOUT;
            int j  = idx % NOUT;
            int kg = kk * 32 + kp * 2;
            float w0, w1;
            if (kg < 64) { w0 = W1[kg * NOUT + j];        w1 = W1[(kg + 1) * NOUT + j]; }
            else         { w0 = W2[(kg - 64) * NOUT + j]; w1 = W2[(kg - 63) * NOUT + j]; }
            Bs2[kp][j] = make_float2(w0, w1);
        }
        __syncthreads();

        #pragma unroll
        for (int kp = 0; kp < 16; kp++) {
            ull a[4], b[4];
            #pragma unroll
            for (int i = 0; i < 4; i++)  a[i]  = *(const ull*)&As2[r * 4 + i][kp];
            #pragma unroll
            for (int jj = 0; jj < 4; jj++) b[jj] = *(const ull*)&Bs2[kp][c + jj * CQ];
            #pragma unroll
            for (int i = 0; i < 4; i++)
                #pragma unroll
                for (int jj = 0; jj < 4; jj++)
                    ffma2(acc[i][jj], a[i], b[jj]);
        }
        __syncthreads();
    }

    float* OUT = (LAYER == 1) ? g_h1 : g_h2;
    #pragma unroll
    for (int i = 0; i < 4; i++) {
        int node = blockBase + r * 4 + i;
        float v[4];
        float sq = 0.f;
        #pragma unroll
        for (int jj = 0; jj < 4; jj++) {
            ull x = acc[i][jj];
            float lo = __uint_as_float((unsigned)(x & 0xffffffffull));
            float hi = __uint_as_float((unsigned)(x >> 32));
            float s = lo + hi + bsum[jj];
            s = (s >= 0.f) ? s : 0.01f * s;
            v[jj] = s;
            sq = fmaf(s, s, sq);
        }
        #pragma unroll
        for (int off = CQ / 2; off > 0; off >>= 1)
            sq += __shfl_xor_sync(0xffffffffu, sq, off);
        float inv = 1.f / fmaxf(sqrtf(sq), 1e-12f);
        if (node < N_NODES) {
            #pragma unroll
            for (int jj = 0; jj < 4; jj++)
                OUT[(size_t)node * NOUT + c + jj * CQ] = v[jj] * inv;
        }
    }
}

// ---------------- scoring: one warp per batch element ----------------------
__global__ void __launch_bounds__(256) k_score(const float* __restrict__ uw,
                                               const float* __restrict__ ew,
                                               const int* __restrict__ uid,
                                               const int* __restrict__ pid,
                                               const int* __restrict__ nid,
                                               float* __restrict__ out) {
    int gidx = blockIdx.x * 256 + threadIdx.x;
    int b = gidx >> 5;
    int l = gidx & 31;
    if (b >= BATCH) return;
    int u  = uid[b];
    int pe = pid[b];
    int ne = nid[b];
    int p  = N_USERS + pe;
    int q  = N_USERS + ne;

    const float* fu = uw + (size_t)u * 64;
    const float* fp = ew + (size_t)pe * 64;
    const float* fq = ew + (size_t)ne * 64;

    float sp = 0.f, sn = 0.f;
    #pragma unroll
    for (int r = 0; r < 2; r++) {
        int cidx = l + r * 32;
        float a = fu[cidx];
        sp = fmaf(a, fp[cidx], sp);
        sn = fmaf(a, fq[cidx], sn);
    }
    #pragma unroll
    for (int r = 0; r < 2; r++) {
        int cidx = l + r * 32;
        float a = g_h1[(size_t)u * 64 + cidx];
        sp = fmaf(a, g_h1[(size_t)p * 64 + cidx], sp);
        sn = fmaf(a, g_h1[(size_t)q * 64 + cidx], sn);
    }
    {
        float a = g_h2[(size_t)u * 32 + l];
        sp = fmaf(a, g_h2[(size_t)p * 32 + l], sp);
        sn = fmaf(a, g_h2[(size_t)q * 32 + l], sn);
    }
    #pragma unroll
    for (int o = 16; o > 0; o >>= 1) {
        sp += __shfl_xor_sync(0xffffffffu, sp, o);
        sn += __shfl_xor_sync(0xffffffffu, sn, o);
    }
    if (l == 0) { out[b] = sp; out[BATCH + b] = sn; }
}

// ---------------- launch ---------------------------------------------------
extern "C" void kernel_launch(void* const* d_in, const int* in_sizes, int n_in,
                              void* d_out, int out_size) {
    const float* uw   = (const float*)d_in[0];
    const float* ew   = (const float*)d_in[1];
    const float* W1a  = (const float*)d_in[2];
    const float* b1a  = (const float*)d_in[3];
    const float* W2a  = (const float*)d_in[4];
    const float* b2a  = (const float*)d_in[5];
    const float* W1b  = (const float*)d_in[6];
    const float* b1b  = (const float*)d_in[7];
    const float* W2b  = (const float*)d_in[8];
    const float* b2b  = (const float*)d_in[9];
    const float* values   = (const float*)d_in[10];
    const int*   target   = (const int*)d_in[11];
    const int*   neighbor = (const int*)d_in[12];
    const int*   uid      = (const int*)d_in[13];
    const int*   pid      = (const int*)d_in[14];
    const int*   nid      = (const int*)d_in[15];
    float* out = (float*)d_out;

    // CSR build (once; reused by both layers)
    k_zero_counts<<<(N_NODES / 4 + 255) / 256, 256>>>();
    k_count<<<N_EDGES / 256, 256>>>(target);
    k_scan<<<1, 1024>>>();
    k_scatter<<<N_EDGES / 256, 256>>>(target, neighbor, values);

    // Layer 1
    k_gather<1><<<N_NODES / 8, 256>>>(uw, ew);
    k_dense<1><<<N_NODES / 64, 256>>>(uw, ew, W1a, b1a, W2a, b2a);

    // Layer 2
    k_gather<2><<<N_NODES / 8, 256>>>(uw, ew);
    k_dense<2><<<(N_NODES + 127) / 128, 256>>>(uw, ew, W1b, b1b, W2b, b2b);

    // Scores
    k_score<<<(BATCH * 32) / 256, 256>>>(uw, ew, uid, pid, nid, out);
}

// round 5
// speedup vs baseline: 1.1472x; 1.1472x over previous
#include <cuda_runtime.h>
#include <cstdint>

#define N_USERS    50000
#define N_ENTITIES 150000
#define N_NODES    200000
#define N_EDGES    3200000
#define BATCH      4096

typedef unsigned long long ull;

// ---------------- scratch (device globals; no allocation allowed) ----------
__device__ __align__(16) float g_hneigh[(size_t)N_NODES * 64];
__device__ __align__(16) float g_h1[(size_t)N_NODES * 64];
__device__ __align__(16) float g_h2[(size_t)N_NODES * 32];
__device__ __align__(16) int   g_count[N_NODES];
__device__ __align__(16) int   g_rowstart[N_NODES + 4];
__device__ __align__(16) int   g_cursor[N_NODES + 4];
__device__ __align__(16) int2  g_srt[N_EDGES];      // {neighbor, value-bits} sorted by target

__device__ __forceinline__ const float* feat0_row(const float* uw, const float* ew, int n) {
    return (n < N_USERS) ? (uw + (size_t)n * 64) : (ew + (size_t)(n - N_USERS) * 64);
}

__device__ __forceinline__ void ffma2(ull& d, ull a, ull b) {
    asm("fma.rn.f32x2 %0, %1, %2, %0;" : "+l"(d) : "l"(a), "l"(b));
}

// ---------------- CSR build ------------------------------------------------
__global__ void __launch_bounds__(256) k_zero_counts() {
    int i = blockIdx.x * 256 + threadIdx.x;           // int4 index
    if (i < N_NODES / 4) ((int4*)g_count)[i] = make_int4(0, 0, 0, 0);
}

__global__ void __launch_bounds__(256) k_count(const int* __restrict__ target) {
    int e = blockIdx.x * 256 + threadIdx.x;           // grid exact: 3.2M/256
    atomicAdd(&g_count[__ldcs(target + e)], 1);       // RED.ADD, no return
}

// Single-block scan; int4 loads in both passes.
__global__ void __launch_bounds__(1024) k_scan() {
    const int CH = 196;                               // 1024*196 >= N_NODES
    __shared__ int sa[1024], sb[1024];
    int t = threadIdx.x;
    int beg = t * CH;
    int end = beg + CH; if (end > N_NODES) end = N_NODES;
    int sum = 0;
    #pragma unroll 7
    for (int i4 = 0; i4 < CH / 4; i4++) {
        int idx = beg + i4 * 4;
        if (idx < end) {
            int4 v = ((const int4*)g_count)[idx >> 2];
            sum += v.x + v.y + v.z + v.w;
        }
    }
    sa[t] = sum;
    __syncthreads();
    int* src = sa; int* dst = sb;
    for (int off = 1; off < 1024; off <<= 1) {
        dst[t] = (t >= off) ? src[t] + src[t - off] : src[t];
        __syncthreads();
        int* tmp = src; src = dst; dst = tmp;
    }
    int run = (t > 0) ? src[t - 1] : 0;               // exclusive prefix
    #pragma unroll 7
    for (int i4 = 0; i4 < CH / 4; i4++) {
        int idx = beg + i4 * 4;
        if (idx < end) {
            int4 v = ((const int4*)g_count)[idx >> 2];
            int4 rs;
            rs.x = run;
            rs.y = rs.x + v.x;
            rs.z = rs.y + v.y;
            rs.w = rs.z + v.z;
            run  = rs.w + v.w;
            ((int4*)g_rowstart)[idx >> 2] = rs;
            ((int4*)g_cursor)[idx >> 2]   = rs;
        }
    }
    if (t == 1023) g_rowstart[N_NODES] = N_EDGES;
}

__global__ void __launch_bounds__(256) k_scatter(const int* __restrict__ target,
                                                const int* __restrict__ neighbor,
                                                const float* __restrict__ values) {
    int e = blockIdx.x * 256 + threadIdx.x;           // grid exact
    int t = __ldcs(target + e);
    int2 rec = make_int2(__ldcs(neighbor + e), __float_as_int(__ldcs(values + e)));
    int pos = atomicAdd(&g_cursor[t], 1);
    __stcs((int2*)&g_srt[pos], rec);
}

// ---------------- CSR gather: h_neigh[n] = sum_e feat[nb_e]*v_e -----------
// One warp per node: 16 lanes = float4 chunks, 2 edges in flight (halves).
// srt is read-once -> ldcs; hneigh is write-once -> stcs (protects the
// feature table's L2 residency).
template <int LAYER>
__global__ void __launch_bounds__(256) k_gather(const float* __restrict__ uw,
                                                const float* __restrict__ ew) {
    int n = (blockIdx.x * 256 + threadIdx.x) >> 5;    // grid exact: 25000*8 warps
    int lane = threadIdx.x & 31;
    int c = lane & 15, half = lane >> 4;
    int base = g_rowstart[n];
    int end  = g_rowstart[n + 1];
    float4 acc = make_float4(0.f, 0.f, 0.f, 0.f);
    for (int i = base + half; i < end; i += 2) {
        int2 e = __ldcs((const int2*)&g_srt[i]);
        float v = __int_as_float(e.y);
        const float* src = (LAYER == 1) ? feat0_row(uw, ew, e.x)
                                        : (g_h1 + (size_t)e.x * 64);
        float4 f = *(const float4*)(src + c * 4);
        acc.x = fmaf(f.x, v, acc.x);
        acc.y = fmaf(f.y, v, acc.y);
        acc.z = fmaf(f.z, v, acc.z);
        acc.w = fmaf(f.w, v, acc.w);
    }
    acc.x += __shfl_xor_sync(0xffffffffu, acc.x, 16);
    acc.y += __shfl_xor_sync(0xffffffffu, acc.y, 16);
    acc.z += __shfl_xor_sync(0xffffffffu, acc.z, 16);
    acc.w += __shfl_xor_sync(0xffffffffu, acc.w, 16);
    if (half == 0)
        __stcs((float4*)(g_hneigh + (size_t)n * 64 + c * 4), acc);
}

// ---------------- dense layer as register-tiled GEMM -----------------------
// out = leakyrelu( [s|p] @ [W1;W2] + b1 + b2 ), then row-l2norm.
// K = 128 in 2 super-chunks of 64: super ss covers feature cols
// [ss*32, ss*32+32): s-pairs -> kp 0..15, p-pairs -> kp 16..31. Each f/g
// float4 is loaded from gmem exactly once.
// LAYER=1: NOUT=64, TM=64.  LAYER=2: NOUT=32, TM=128.
template <int LAYER>
__global__ void __launch_bounds__(256) k_dense(const float* __restrict__ uw,
                                               const float* __restrict__ ew,
                                               const float* __restrict__ W1,
                                               const float* __restrict__ b1,
                                               const float* __restrict__ W2,
                                               const float* __restrict__ b2) {
    constexpr int NOUT = (LAYER == 1) ? 64 : 32;
    constexpr int CQ   = NOUT / 4;          // 16 / 8
    constexpr int TM   = (256 / CQ) * 4;    // 64 / 128
    constexpr int AP   = 33;                // A row pitch in float2 (pad: banks differ per m)

    __shared__ __align__(16) float2 As2[TM * AP];    // [m][kp 0..31] (s:0..15, p:16..31)
    __shared__ __align__(16) float2 Bs2[32 * NOUT];  // [kp][col]

    int tid = threadIdx.x;
    int r = tid / CQ;       // node quad
    int c = tid % CQ;       // col within group
    int blockBase = blockIdx.x * TM;

    float bsum[4];
    #pragma unroll
    for (int jj = 0; jj < 4; jj++) {
        int j = c + jj * CQ;
        bsum[jj] = b1[j] + b2[j];
    }

    ull acc[4][4];
    #pragma unroll
    for (int i = 0; i < 4; i++)
        #pragma unroll
        for (int jj = 0; jj < 4; jj++) acc[i][jj] = 0ull;

    #pragma unroll
    for (int ss = 0; ss < 2; ss++) {
        int base_col = ss * 32;
        // ---- stage A: load f,g once; emit both s and p pairs --------------
        for (int idx = tid; idx < TM * 8; idx += 256) {     // float4 granularity
            int m  = idx >> 3;
            int q4 = idx & 7;
            int node = blockBase + m;
            float4 fv = make_float4(0.f, 0.f, 0.f, 0.f);
            float4 gv = fv;
            if (node < N_NODES) {
                const float* fr = (LAYER == 1) ? feat0_row(uw, ew, node)
                                               : (g_h1 + (size_t)node * 64);
                fv = *(const float4*)(fr + base_col + q4 * 4);
                gv = __ldcs((const float4*)(g_hneigh + (size_t)node * 64 + base_col + q4 * 4));
            }
            float2* row = As2 + m * AP;
            row[q4 * 2]          = make_float2(fv.x + gv.x, fv.y + gv.y);
            row[q4 * 2 + 1]      = make_float2(fv.z + gv.z, fv.w + gv.w);
            row[16 + q4 * 2]     = make_float2(fv.x * gv.x, fv.y * gv.y);
            row[16 + q4 * 2 + 1] = make_float2(fv.z * gv.z, fv.w * gv.w);
        }
        // ---- stage B: W1 rows [base_col,base_col+32) -> kp 0..15,
        //               W2 same rows -> kp 16..31 ---------------------------
        for (int idx = tid; idx < 32 * NOUT; idx += 256) {
            int kp = idx / NOUT;
            int j  = idx % NOUT;
            float w0, w1;
            if (kp < 16) {
                int kg = base_col + kp * 2;
                w0 = W1[kg * NOUT + j]; w1 = W1[(kg + 1) * NOUT + j];
            } else {
                int kg = base_col + (kp - 16) * 2;
                w0 = W2[kg * NOUT + j]; w1 = W2[(kg + 1) * NOUT + j];
            }
            Bs2[kp * NOUT + j] = make_float2(w0, w1);
        }
        __syncthreads();

        // ---- mainloop: 32 k-pairs ----------------------------------------
        #pragma unroll 8
        for (int kp = 0; kp < 32; kp++) {
            ull a[4], b[4];
            #pragma unroll
            for (int i = 0; i < 4; i++)  a[i]  = *(const ull*)&As2[(r * 4 + i) * AP + kp];
            #pragma unroll
            for (int jj = 0; jj < 4; jj++) b[jj] = *(const ull*)&Bs2[kp * NOUT + c + jj * CQ];
            #pragma unroll
            for (int i = 0; i < 4; i++)
                #pragma unroll
                for (int jj = 0; jj < 4; jj++)
                    ffma2(acc[i][jj], a[i], b[jj]);
        }
        __syncthreads();
    }

    // ---- epilogue: bias, leaky relu, row l2-norm, store -------------------
    float* OUT = (LAYER == 1) ? g_h1 : g_h2;
    #pragma unroll
    for (int i = 0; i < 4; i++) {
        int node = blockBase + r * 4 + i;
        float v[4];
        float sq = 0.f;
        #pragma unroll
        for (int jj = 0; jj < 4; jj++) {
            ull x = acc[i][jj];
            float lo = __uint_as_float((unsigned)(x & 0xffffffffull));
            float hi = __uint_as_float((unsigned)(x >> 32));
            float s = lo + hi + bsum[jj];
            s = (s >= 0.f) ? s : 0.01f * s;
            v[jj] = s;
            sq = fmaf(s, s, sq);
        }
        #pragma unroll
        for (int off = CQ / 2; off > 0; off >>= 1)
            sq += __shfl_xor_sync(0xffffffffu, sq, off);
        float inv = 1.f / fmaxf(sqrtf(sq), 1e-12f);
        if (node < N_NODES) {
            #pragma unroll
            for (int jj = 0; jj < 4; jj++)
                OUT[(size_t)node * NOUT + c + jj * CQ] = v[jj] * inv;
        }
    }
}

// ---------------- scoring: one warp per batch element ----------------------
__global__ void __launch_bounds__(256) k_score(const float* __restrict__ uw,
                                               const float* __restrict__ ew,
                                               const int* __restrict__ uid,
                                               const int* __restrict__ pid,
                                               const int* __restrict__ nid,
                                               float* __restrict__ out) {
    int gidx = blockIdx.x * 256 + threadIdx.x;
    int b = gidx >> 5;
    int l = gidx & 31;
    if (b >= BATCH) return;
    int u  = uid[b];
    int pe = pid[b];
    int ne = nid[b];
    int p  = N_USERS + pe;
    int q  = N_USERS + ne;

    const float* fu = uw + (size_t)u * 64;
    const float* fp = ew + (size_t)pe * 64;
    const float* fq = ew + (size_t)ne * 64;

    float sp = 0.f, sn = 0.f;
    #pragma unroll
    for (int r = 0; r < 2; r++) {
        int cidx = l + r * 32;
        float a = fu[cidx];
        sp = fmaf(a, fp[cidx], sp);
        sn = fmaf(a, fq[cidx], sn);
    }
    #pragma unroll
    for (int r = 0; r < 2; r++) {
        int cidx = l + r * 32;
        float a = g_h1[(size_t)u * 64 + cidx];
        sp = fmaf(a, g_h1[(size_t)p * 64 + cidx], sp);
        sn = fmaf(a, g_h1[(size_t)q * 64 + cidx], sn);
    }
    {
        float a = g_h2[(size_t)u * 32 + l];
        sp = fmaf(a, g_h2[(size_t)p * 32 + l], sp);
        sn = fmaf(a, g_h2[(size_t)q * 32 + l], sn);
    }
    #pragma unroll
    for (int o = 16; o > 0; o >>= 1) {
        sp += __shfl_xor_sync(0xffffffffu, sp, o);
        sn += __shfl_xor_sync(0xffffffffu, sn, o);
    }
    if (l == 0) { out[b] = sp; out[BATCH + b] = sn; }
}

// ---------------- launch ---------------------------------------------------
extern "C" void kernel_launch(void* const* d_in, const int* in_sizes, int n_in,
                              void* d_out, int out_size) {
    const float* uw   = (const float*)d_in[0];
    const float* ew   = (const float*)d_in[1];
    const float* W1a  = (const float*)d_in[2];
    const float* b1a  = (const float*)d_in[3];
    const float* W2a  = (const float*)d_in[4];
    const float* b2a  = (const float*)d_in[5];
    const float* W1b  = (const float*)d_in[6];
    const float* b1b  = (const float*)d_in[7];
    const float* W2b  = (const float*)d_in[8];
    const float* b2b  = (const float*)d_in[9];
    const float* values   = (const float*)d_in[10];
    const int*   target   = (const int*)d_in[11];
    const int*   neighbor = (const int*)d_in[12];
    const int*   uid      = (const int*)d_in[13];
    const int*   pid      = (const int*)d_in[14];
    const int*   nid      = (const int*)d_in[15];
    float* out = (float*)d_out;

    // CSR build (once; reused by both layers)
    k_zero_counts<<<(N_NODES / 4 + 255) / 256, 256>>>();
    k_count<<<N_EDGES / 256, 256>>>(target);
    k_scan<<<1, 1024>>>();
    k_scatter<<<N_EDGES / 256, 256>>>(target, neighbor, values);

    // Layer 1
    k_gather<1><<<N_NODES / 8, 256>>>(uw, ew);
    k_dense<1><<<N_NODES / 64, 256>>>(uw, ew, W1a, b1a, W2a, b2a);

    // Layer 2
    k_gather<2><<<N_NODES / 8, 256>>>(uw, ew);
    k_dense<2><<<(N_NODES + 127) / 128, 256>>>(uw, ew, W1b, b1b, W2b, b2b);

    // Scores
    k_score<<<(BATCH * 32) / 256, 256>>>(uw, ew, uid, pid, nid, out);
}

// round 6
// speedup vs baseline: 1.2007x; 1.0466x over previous
#include <cuda_runtime.h>
#include <cuda_fp16.h>
#include <cstdint>

#define N_USERS    50000
#define N_ENTITIES 150000
#define N_NODES    200000
#define N_EDGES    3200000
#define BATCH      4096

typedef unsigned long long ull;

// ---------------- scratch (device globals; no allocation allowed) ----------
__device__ __align__(16) float  g_hneigh[(size_t)N_NODES * 64];
__device__ __align__(16) float  g_h1[(size_t)N_NODES * 64];
__device__ __align__(16) float  g_h2[(size_t)N_NODES * 32];
__device__ __align__(16) __half g_feat16[(size_t)N_NODES * 64];  // fp16 ego features
__device__ __align__(16) __half g_h116[(size_t)N_NODES * 64];    // fp16 copy of h1
__device__ __align__(16) int    g_count[N_NODES];
__device__ __align__(16) int    g_rowstart[N_NODES + 4];
__device__ __align__(16) int    g_cursor[N_NODES + 4];
__device__ __align__(16) int2   g_srt[N_EDGES];     // {neighbor, value-bits} sorted by target

__device__ __forceinline__ const float* feat0_row(const float* uw, const float* ew, int n) {
    return (n < N_USERS) ? (uw + (size_t)n * 64) : (ew + (size_t)(n - N_USERS) * 64);
}

__device__ __forceinline__ void ffma2(ull& d, ull a, ull b) {
    asm("fma.rn.f32x2 %0, %1, %2, %0;" : "+l"(d) : "l"(a), "l"(b));
}

// ---------------- fp16 feature table build ---------------------------------
// Each thread converts 8 floats -> 8 halves (uint4 store). Grid exact: 1.6M/256.
__global__ void __launch_bounds__(256) k_tofp16(const float* __restrict__ uw,
                                                const float* __restrict__ ew) {
    size_t i = (size_t)blockIdx.x * 256 + threadIdx.x;
    size_t base = i * 8;                       // global element index
    int node = (int)(base >> 6);
    int col  = (int)(base & 63);
    const float* row = feat0_row(uw, ew, node);
    float4 a = *(const float4*)(row + col);
    float4 b = *(const float4*)(row + col + 4);
    __half2 h0 = __floats2half2_rn(a.x, a.y);
    __half2 h1 = __floats2half2_rn(a.z, a.w);
    __half2 h2 = __floats2half2_rn(b.x, b.y);
    __half2 h3 = __floats2half2_rn(b.z, b.w);
    uint4 out;
    out.x = *(const unsigned*)&h0;
    out.y = *(const unsigned*)&h1;
    out.z = *(const unsigned*)&h2;
    out.w = *(const unsigned*)&h3;
    *(uint4*)(g_feat16 + base) = out;
}

// ---------------- CSR build ------------------------------------------------
__global__ void __launch_bounds__(256) k_zero_counts() {
    int i = blockIdx.x * 256 + threadIdx.x;           // int4 index
    if (i < N_NODES / 4) ((int4*)g_count)[i] = make_int4(0, 0, 0, 0);
}

__global__ void __launch_bounds__(256) k_count(const int* __restrict__ target) {
    int e = blockIdx.x * 256 + threadIdx.x;           // grid exact: 3.2M/256
    atomicAdd(&g_count[__ldcs(target + e)], 1);       // RED.ADD, no return
}

// Single-block scan; int4 loads in both passes.
__global__ void __launch_bounds__(1024) k_scan() {
    const int CH = 196;
    __shared__ int sa[1024], sb[1024];
    int t = threadIdx.x;
    int beg = t * CH;
    int end = beg + CH; if (end > N_NODES) end = N_NODES;
    int sum = 0;
    #pragma unroll 7
    for (int i4 = 0; i4 < CH / 4; i4++) {
        int idx = beg + i4 * 4;
        if (idx < end) {
            int4 v = ((const int4*)g_count)[idx >> 2];
            sum += v.x + v.y + v.z + v.w;
        }
    }
    sa[t] = sum;
    __syncthreads();
    int* src = sa; int* dst = sb;
    for (int off = 1; off < 1024; off <<= 1) {
        dst[t] = (t >= off) ? src[t] + src[t - off] : src[t];
        __syncthreads();
        int* tmp = src; src = dst; dst = tmp;
    }
    int run = (t > 0) ? src[t - 1] : 0;
    #pragma unroll 7
    for (int i4 = 0; i4 < CH / 4; i4++) {
        int idx = beg + i4 * 4;
        if (idx < end) {
            int4 v = ((const int4*)g_count)[idx >> 2];
            int4 rs;
            rs.x = run;
            rs.y = rs.x + v.x;
            rs.z = rs.y + v.y;
            rs.w = rs.z + v.z;
            run  = rs.w + v.w;
            ((int4*)g_rowstart)[idx >> 2] = rs;
            ((int4*)g_cursor)[idx >> 2]   = rs;
        }
    }
    if (t == 1023) g_rowstart[N_NODES] = N_EDGES;
}

__global__ void __launch_bounds__(256) k_scatter(const int* __restrict__ target,
                                                const int* __restrict__ neighbor,
                                                const float* __restrict__ values) {
    int e = blockIdx.x * 256 + threadIdx.x;           // grid exact
    int t = __ldcs(target + e);
    int2 rec = make_int2(__ldcs(neighbor + e), __float_as_int(__ldcs(values + e)));
    int pos = atomicAdd(&g_cursor[t], 1);
    __stcs((int2*)&g_srt[pos], rec);
}

// ---------------- CSR gather (fp16 rows): hneigh[n] = sum feat16[nb]*v -----
// One warp per node: 16 lanes x uint2 (4 halves = 8B) covers the 128B row,
// halves of the warp take alternate edges. Accumulate fp32.
template <int LAYER>
__global__ void __launch_bounds__(256) k_gather() {
    int n = (blockIdx.x * 256 + threadIdx.x) >> 5;    // grid exact: 25000*8 warps
    int lane = threadIdx.x & 31;
    int c = lane & 15, half = lane >> 4;
    const __half* TAB = (LAYER == 1) ? g_feat16 : g_h116;
    int base = g_rowstart[n];
    int end  = g_rowstart[n + 1];
    float4 acc = make_float4(0.f, 0.f, 0.f, 0.f);
    for (int i = base + half; i < end; i += 2) {
        int2 e = __ldcs((const int2*)&g_srt[i]);
        float v = __int_as_float(e.y);
        uint2 hv = *(const uint2*)(TAB + (size_t)e.x * 64 + c * 4);
        float2 f01 = __half22float2(*(const __half2*)&hv.x);
        float2 f23 = __half22float2(*(const __half2*)&hv.y);
        acc.x = fmaf(f01.x, v, acc.x);
        acc.y = fmaf(f01.y, v, acc.y);
        acc.z = fmaf(f23.x, v, acc.z);
        acc.w = fmaf(f23.y, v, acc.w);
    }
    acc.x += __shfl_xor_sync(0xffffffffu, acc.x, 16);
    acc.y += __shfl_xor_sync(0xffffffffu, acc.y, 16);
    acc.z += __shfl_xor_sync(0xffffffffu, acc.z, 16);
    acc.w += __shfl_xor_sync(0xffffffffu, acc.w, 16);
    if (half == 0)
        __stcs((float4*)(g_hneigh + (size_t)n * 64 + c * 4), acc);
}

// ---------------- dense layer as register-tiled GEMM -----------------------
// out = leakyrelu( [s|p] @ [W1;W2] + b1 + b2 ), then row-l2norm.
// K = 128 in 2 super-chunks of 64 (each f/g float4 loaded once).
// LAYER=1 additionally emits fp16 copy of h1 for gather2.
template <int LAYER>
__global__ void __launch_bounds__(256) k_dense(const float* __restrict__ uw,
                                               const float* __restrict__ ew,
                                               const float* __restrict__ W1,
                                               const float* __restrict__ b1,
                                               const float* __restrict__ W2,
                                               const float* __restrict__ b2) {
    constexpr int NOUT = (LAYER == 1) ? 64 : 32;
    constexpr int CQ   = NOUT / 4;          // 16 / 8
    constexpr int TM   = (256 / CQ) * 4;    // 64 / 128
    constexpr int AP   = 33;                // A row pitch in float2

    __shared__ __align__(16) float2 As2[TM * AP];
    __shared__ __align__(16) float2 Bs2[32 * NOUT];

    int tid = threadIdx.x;
    int r = tid / CQ;
    int c = tid % CQ;
    int blockBase = blockIdx.x * TM;

    float bsum[4];
    #pragma unroll
    for (int jj = 0; jj < 4; jj++) {
        int j = c + jj * CQ;
        bsum[jj] = b1[j] + b2[j];
    }

    ull acc[4][4];
    #pragma unroll
    for (int i = 0; i < 4; i++)
        #pragma unroll
        for (int jj = 0; jj < 4; jj++) acc[i][jj] = 0ull;

    #pragma unroll
    for (int ss = 0; ss < 2; ss++) {
        int base_col = ss * 32;
        for (int idx = tid; idx < TM * 8; idx += 256) {
            int m  = idx >> 3;
            int q4 = idx & 7;
            int node = blockBase + m;
            float4 fv = make_float4(0.f, 0.f, 0.f, 0.f);
            float4 gv = fv;
            if (node < N_NODES) {
                const float* fr = (LAYER == 1) ? feat0_row(uw, ew, node)
                                               : (g_h1 + (size_t)node * 64);
                fv = *(const float4*)(fr + base_col + q4 * 4);
                gv = __ldcs((const float4*)(g_hneigh + (size_t)node * 64 + base_col + q4 * 4));
            }
            float2* row = As2 + m * AP;
            row[q4 * 2]          = make_float2(fv.x + gv.x, fv.y + gv.y);
            row[q4 * 2 + 1]      = make_float2(fv.z + gv.z, fv.w + gv.w);
            row[16 + q4 * 2]     = make_float2(fv.x * gv.x, fv.y * gv.y);
            row[16 + q4 * 2 + 1] = make_float2(fv.z * gv.z, fv.w * gv.w);
        }
        for (int idx = tid; idx < 32 * NOUT; idx += 256) {
            int kp = idx / NOUT;
            int j  = idx % NOUT;
            float w0, w1;
            if (kp < 16) {
                int kg = base_col + kp * 2;
                w0 = W1[kg * NOUT + j]; w1 = W1[(kg + 1) * NOUT + j];
            } else {
                int kg = base_col + (kp - 16) * 2;
                w0 = W2[kg * NOUT + j]; w1 = W2[(kg + 1) * NOUT + j];
            }
            Bs2[kp * NOUT + j] = make_float2(w0, w1);
        }
        __syncthreads();

        #pragma unroll 8
        for (int kp = 0; kp < 32; kp++) {
            ull a[4], b[4];
            #pragma unroll
            for (int i = 0; i < 4; i++)  a[i]  = *(const ull*)&As2[(r * 4 + i) * AP + kp];
            #pragma unroll
            for (int jj = 0; jj < 4; jj++) b[jj] = *(const ull*)&Bs2[kp * NOUT + c + jj * CQ];
            #pragma unroll
            for (int i = 0; i < 4; i++)
                #pragma unroll
                for (int jj = 0; jj < 4; jj++)
                    ffma2(acc[i][jj], a[i], b[jj]);
        }
        __syncthreads();
    }

    float* OUT = (LAYER == 1) ? g_h1 : g_h2;
    #pragma unroll
    for (int i = 0; i < 4; i++) {
        int node = blockBase + r * 4 + i;
        float v[4];
        float sq = 0.f;
        #pragma unroll
        for (int jj = 0; jj < 4; jj++) {
            ull x = acc[i][jj];
            float lo = __uint_as_float((unsigned)(x & 0xffffffffull));
            float hi = __uint_as_float((unsigned)(x >> 32));
            float s = lo + hi + bsum[jj];
            s = (s >= 0.f) ? s : 0.01f * s;
            v[jj] = s;
            sq = fmaf(s, s, sq);
        }
        #pragma unroll
        for (int off = CQ / 2; off > 0; off >>= 1)
            sq += __shfl_xor_sync(0xffffffffu, sq, off);
        float inv = 1.f / fmaxf(sqrtf(sq), 1e-12f);
        if (node < N_NODES) {
            #pragma unroll
            for (int jj = 0; jj < 4; jj++) {
                float o = v[jj] * inv;
                OUT[(size_t)node * NOUT + c + jj * CQ] = o;
                if (LAYER == 1)
                    g_h116[(size_t)node * 64 + c + jj * CQ] = __float2half_rn(o);
            }
        }
    }
}

// ---------------- scoring: one warp per batch element ----------------------
__global__ void __launch_bounds__(256) k_score(const float* __restrict__ uw,
                                               const float* __restrict__ ew,
                                               const int* __restrict__ uid,
                                               const int* __restrict__ pid,
                                               const int* __restrict__ nid,
                                               float* __restrict__ out) {
    int gidx = blockIdx.x * 256 + threadIdx.x;
    int b = gidx >> 5;
    int l = gidx & 31;
    if (b >= BATCH) return;
    int u  = uid[b];
    int pe = pid[b];
    int ne = nid[b];
    int p  = N_USERS + pe;
    int q  = N_USERS + ne;

    const float* fu = uw + (size_t)u * 64;
    const float* fp = ew + (size_t)pe * 64;
    const float* fq = ew + (size_t)ne * 64;

    float sp = 0.f, sn = 0.f;
    #pragma unroll
    for (int r = 0; r < 2; r++) {
        int cidx = l + r * 32;
        float a = fu[cidx];
        sp = fmaf(a, fp[cidx], sp);
        sn = fmaf(a, fq[cidx], sn);
    }
    #pragma unroll
    for (int r = 0; r < 2; r++) {
        int cidx = l + r * 32;
        float a = g_h1[(size_t)u * 64 + cidx];
        sp = fmaf(a, g_h1[(size_t)p * 64 + cidx], sp);
        sn = fmaf(a, g_h1[(size_t)q * 64 + cidx], sn);
    }
    {
        float a = g_h2[(size_t)u * 32 + l];
        sp = fmaf(a, g_h2[(size_t)p * 32 + l], sp);
        sn = fmaf(a, g_h2[(size_t)q * 32 + l], sn);
    }
    #pragma unroll
    for (int o = 16; o > 0; o >>= 1) {
        sp += __shfl_xor_sync(0xffffffffu, sp, o);
        sn += __shfl_xor_sync(0xffffffffu, sn, o);
    }
    if (l == 0) { out[b] = sp; out[BATCH + b] = sn; }
}

// ---------------- launch ---------------------------------------------------
extern "C" void kernel_launch(void* const* d_in, const int* in_sizes, int n_in,
                              void* d_out, int out_size) {
    const float* uw   = (const float*)d_in[0];
    const float* ew   = (const float*)d_in[1];
    const float* W1a  = (const float*)d_in[2];
    const float* b1a  = (const float*)d_in[3];
    const float* W2a  = (const float*)d_in[4];
    const float* b2a  = (const float*)d_in[5];
    const float* W1b  = (const float*)d_in[6];
    const float* b1b  = (const float*)d_in[7];
    const float* W2b  = (const float*)d_in[8];
    const float* b2b  = (const float*)d_in[9];
    const float* values   = (const float*)d_in[10];
    const int*   target   = (const int*)d_in[11];
    const int*   neighbor = (const int*)d_in[12];
    const int*   uid      = (const int*)d_in[13];
    const int*   pid      = (const int*)d_in[14];
    const int*   nid      = (const int*)d_in[15];
    float* out = (float*)d_out;

    // fp16 feature table + CSR build
    k_tofp16<<<(N_NODES * 64 / 8) / 256, 256>>>(uw, ew);
    k_zero_counts<<<(N_NODES / 4 + 255) / 256, 256>>>();
    k_count<<<N_EDGES / 256, 256>>>(target);
    k_scan<<<1, 1024>>>();
    k_scatter<<<N_EDGES / 256, 256>>>(target, neighbor, values);

    // Layer 1
    k_gather<1><<<N_NODES / 8, 256>>>();
    k_dense<1><<<N_NODES / 64, 256>>>(uw, ew, W1a, b1a, W2a, b2a);

    // Layer 2
    k_gather<2><<<N_NODES / 8, 256>>>();
    k_dense<2><<<(N_NODES + 127) / 128, 256>>>(uw, ew, W1b, b1b, W2b, b2b);

    // Scores
    k_score<<<(BATCH * 32) / 256, 256>>>(uw, ew, uid, pid, nid, out);
}

// round 7
// speedup vs baseline: 1.5071x; 1.2552x over previous
#include <cuda_runtime.h>
#include <cuda_fp16.h>
#include <cstdint>

#define N_USERS    50000
#define N_ENTITIES 150000
#define N_NODES    200000
#define N_EDGES    3200000
#define BATCH      4096
#define SCAN_BLOCKS 196            // 196*1024 = 200704 >= N_NODES

typedef unsigned long long ull;

// ---------------- scratch (device globals; no allocation allowed) ----------
__device__ __align__(16) float  g_hneigh[(size_t)N_NODES * 64];
__device__ __align__(16) float  g_h1[(size_t)N_NODES * 64];
__device__ __align__(16) float  g_h2[(size_t)N_NODES * 32];
__device__ __align__(16) __half g_feat16[(size_t)N_NODES * 64];  // fp16 ego features
__device__ __align__(16) __half g_h116[(size_t)N_NODES * 64];    // fp16 copy of h1
__device__ __align__(16) int    g_count[N_NODES];
__device__ __align__(16) int    g_rowstart[N_NODES + 4];
__device__ __align__(16) int    g_cursor[N_NODES + 4];
__device__ __align__(16) int    g_bsum[SCAN_BLOCKS];
__device__ __align__(16) int    g_boff[SCAN_BLOCKS];
__device__ __align__(16) int2   g_srt[N_EDGES];     // {neighbor, value-bits} sorted by target

__device__ __forceinline__ const float* feat0_row(const float* uw, const float* ew, int n) {
    return (n < N_USERS) ? (uw + (size_t)n * 64) : (ew + (size_t)(n - N_USERS) * 64);
}

__device__ __forceinline__ void ffma2(ull& d, ull a, ull b) {
    asm("fma.rn.f32x2 %0, %1, %2, %0;" : "+l"(d) : "l"(a), "l"(b));
}

// ---------------- fp16 feature table build ---------------------------------
__global__ void __launch_bounds__(256) k_tofp16(const float* __restrict__ uw,
                                                const float* __restrict__ ew) {
    size_t i = (size_t)blockIdx.x * 256 + threadIdx.x;
    size_t base = i * 8;
    int node = (int)(base >> 6);
    int col  = (int)(base & 63);
    const float* row = feat0_row(uw, ew, node);
    float4 a = *(const float4*)(row + col);
    float4 b = *(const float4*)(row + col + 4);
    __half2 h0 = __floats2half2_rn(a.x, a.y);
    __half2 h1 = __floats2half2_rn(a.z, a.w);
    __half2 h2 = __floats2half2_rn(b.x, b.y);
    __half2 h3 = __floats2half2_rn(b.z, b.w);
    uint4 out;
    out.x = *(const unsigned*)&h0;
    out.y = *(const unsigned*)&h1;
    out.z = *(const unsigned*)&h2;
    out.w = *(const unsigned*)&h3;
    *(uint4*)(g_feat16 + base) = out;
}

// ---------------- CSR build ------------------------------------------------
__global__ void __launch_bounds__(256) k_zero_counts() {
    int i = blockIdx.x * 256 + threadIdx.x;
    if (i < N_NODES / 4) ((int4*)g_count)[i] = make_int4(0, 0, 0, 0);
}

__global__ void __launch_bounds__(256) k_count(const int* __restrict__ target) {
    int e = blockIdx.x * 256 + threadIdx.x;           // grid exact: 3.2M/256
    atomicAdd(&g_count[__ldcs(target + e)], 1);
}

// Phase 1: per-block exclusive scan of 1024 counts; local prefix -> rowstart.
__global__ void __launch_bounds__(1024) k_scan1() {
    __shared__ int warp_tot[32];
    int i = blockIdx.x * 1024 + threadIdx.x;
    int lane = threadIdx.x & 31, w = threadIdx.x >> 5;
    int v = (i < N_NODES) ? g_count[i] : 0;
    int x = v;
    #pragma unroll
    for (int o = 1; o < 32; o <<= 1) {
        int y = __shfl_up_sync(0xffffffffu, x, o);
        if (lane >= o) x += y;
    }
    if (lane == 31) warp_tot[w] = x;
    __syncthreads();
    if (w == 0) {
        int t = warp_tot[lane];
        #pragma unroll
        for (int o = 1; o < 32; o <<= 1) {
            int y = __shfl_up_sync(0xffffffffu, t, o);
            if (lane >= o) t += y;
        }
        warp_tot[lane] = t;
    }
    __syncthreads();
    int excl = x - v + ((w > 0) ? warp_tot[w - 1] : 0);
    if (i < N_NODES) g_rowstart[i] = excl;
    if (threadIdx.x == 1023) g_bsum[blockIdx.x] = excl + v;   // block total
}

// Phase 2: scan the 196 block totals (tiny).
__global__ void __launch_bounds__(256) k_scan2() {
    __shared__ int s[SCAN_BLOCKS];
    int t = threadIdx.x;
    if (t < SCAN_BLOCKS) s[t] = g_bsum[t];
    __syncthreads();
    if (t == 0) {
        int run = 0;
        for (int b = 0; b < SCAN_BLOCKS; b++) { int c = s[b]; s[b] = run; run += c; }
    }
    __syncthreads();
    if (t < SCAN_BLOCKS) g_boff[t] = s[t];
}

// Phase 3: add block offsets; materialize rowstart + cursor.
__global__ void __launch_bounds__(1024) k_scan3() {
    int i = blockIdx.x * 1024 + threadIdx.x;
    if (i < N_NODES) {
        int v = g_rowstart[i] + g_boff[blockIdx.x];
        g_rowstart[i] = v;
        g_cursor[i]   = v;
    }
    if (i == 0) g_rowstart[N_NODES] = N_EDGES;
}

__global__ void __launch_bounds__(256) k_scatter(const int* __restrict__ target,
                                                const int* __restrict__ neighbor,
                                                const float* __restrict__ values) {
    int e = blockIdx.x * 256 + threadIdx.x;           // grid exact
    int t = __ldcs(target + e);
    int2 rec = make_int2(__ldcs(neighbor + e), __float_as_int(__ldcs(values + e)));
    int pos = atomicAdd(&g_cursor[t], 1);
    __stcs((int2*)&g_srt[pos], rec);
}

// ---------------- CSR gather (fp16 rows): hneigh[n] = sum feat16[nb]*v -----
template <int LAYER>
__global__ void __launch_bounds__(256) k_gather() {
    int n = (blockIdx.x * 256 + threadIdx.x) >> 5;    // grid exact: 25000*8 warps
    int lane = threadIdx.x & 31;
    int c = lane & 15, half = lane >> 4;
    const __half* TAB = (LAYER == 1) ? g_feat16 : g_h116;
    int base = g_rowstart[n];
    int end  = g_rowstart[n + 1];
    float4 acc = make_float4(0.f, 0.f, 0.f, 0.f);
    for (int i = base + half; i < end; i += 2) {
        int2 e = __ldcs((const int2*)&g_srt[i]);
        float v = __int_as_float(e.y);
        uint2 hv = *(const uint2*)(TAB + (size_t)e.x * 64 + c * 4);
        float2 f01 = __half22float2(*(const __half2*)&hv.x);
        float2 f23 = __half22float2(*(const __half2*)&hv.y);
        acc.x = fmaf(f01.x, v, acc.x);
        acc.y = fmaf(f01.y, v, acc.y);
        acc.z = fmaf(f23.x, v, acc.z);
        acc.w = fmaf(f23.y, v, acc.w);
    }
    acc.x += __shfl_xor_sync(0xffffffffu, acc.x, 16);
    acc.y += __shfl_xor_sync(0xffffffffu, acc.y, 16);
    acc.z += __shfl_xor_sync(0xffffffffu, acc.z, 16);
    acc.w += __shfl_xor_sync(0xffffffffu, acc.w, 16);
    if (half == 0)
        __stcs((float4*)(g_hneigh + (size_t)n * 64 + c * 4), acc);
}

// ---------------- dense layer as register-tiled GEMM -----------------------
template <int LAYER>
__global__ void __launch_bounds__(256) k_dense(const float* __restrict__ uw,
                                               const float* __restrict__ ew,
                                               const float* __restrict__ W1,
                                               const float* __restrict__ b1,
                                               const float* __restrict__ W2,
                                               const float* __restrict__ b2) {
    constexpr int NOUT = (LAYER == 1) ? 64 : 32;
    constexpr int CQ   = NOUT / 4;          // 16 / 8
    constexpr int TM   = (256 / CQ) * 4;    // 64 / 128
    constexpr int AP   = 33;                // A row pitch in float2

    __shared__ __align__(16) float2 As2[TM * AP];
    __shared__ __align__(16) float2 Bs2[32 * NOUT];

    int tid = threadIdx.x;
    int r = tid / CQ;
    int c = tid % CQ;
    int blockBase = blockIdx.x * TM;

    float bsum[4];
    #pragma unroll
    for (int jj = 0; jj < 4; jj++) {
        int j = c + jj * CQ;
        bsum[jj] = b1[j] + b2[j];
    }

    ull acc[4][4];
    #pragma unroll
    for (int i = 0; i < 4; i++)
        #pragma unroll
        for (int jj = 0; jj < 4; jj++) acc[i][jj] = 0ull;

    #pragma unroll
    for (int ss = 0; ss < 2; ss++) {
        int base_col = ss * 32;
        for (int idx = tid; idx < TM * 8; idx += 256) {
            int m  = idx >> 3;
            int q4 = idx & 7;
            int node = blockBase + m;
            float4 fv = make_float4(0.f, 0.f, 0.f, 0.f);
            float4 gv = fv;
            if (node < N_NODES) {
                const float* fr = (LAYER == 1) ? feat0_row(uw, ew, node)
                                               : (g_h1 + (size_t)node * 64);
                fv = *(const float4*)(fr + base_col + q4 * 4);
                gv = __ldcs((const float4*)(g_hneigh + (size_t)node * 64 + base_col + q4 * 4));
            }
            float2* row = As2 + m * AP;
            row[q4 * 2]          = make_float2(fv.x + gv.x, fv.y + gv.y);
            row[q4 * 2 + 1]      = make_float2(fv.z + gv.z, fv.w + gv.w);
            row[16 + q4 * 2]     = make_float2(fv.x * gv.x, fv.y * gv.y);
            row[16 + q4 * 2 + 1] = make_float2(fv.z * gv.z, fv.w * gv.w);
        }
        for (int idx = tid; idx < 32 * NOUT; idx += 256) {
            int kp = idx / NOUT;
            int j  = idx % NOUT;
            float w0, w1;
            if (kp < 16) {
                int kg = base_col + kp * 2;
                w0 = W1[kg * NOUT + j]; w1 = W1[(kg + 1) * NOUT + j];
            } else {
                int kg = base_col + (kp - 16) * 2;
                w0 = W2[kg * NOUT + j]; w1 = W2[(kg + 1) * NOUT + j];
            }
            Bs2[kp * NOUT + j] = make_float2(w0, w1);
        }
        __syncthreads();

        #pragma unroll 8
        for (int kp = 0; kp < 32; kp++) {
            ull a[4], b[4];
            #pragma unroll
            for (int i = 0; i < 4; i++)  a[i]  = *(const ull*)&As2[(r * 4 + i) * AP + kp];
            #pragma unroll
            for (int jj = 0; jj < 4; jj++) b[jj] = *(const ull*)&Bs2[kp * NOUT + c + jj * CQ];
            #pragma unroll
            for (int i = 0; i < 4; i++)
                #pragma unroll
                for (int jj = 0; jj < 4; jj++)
                    ffma2(acc[i][jj], a[i], b[jj]);
        }
        __syncthreads();
    }

    float* OUT = (LAYER == 1) ? g_h1 : g_h2;
    #pragma unroll
    for (int i = 0; i < 4; i++) {
        int node = blockBase + r * 4 + i;
        float v[4];
        float sq = 0.f;
        #pragma unroll
        for (int jj = 0; jj < 4; jj++) {
            ull x = acc[i][jj];
            float lo = __uint_as_float((unsigned)(x & 0xffffffffull));
            float hi = __uint_as_float((unsigned)(x >> 32));
            float s = lo + hi + bsum[jj];
            s = (s >= 0.f) ? s : 0.01f * s;
            v[jj] = s;
            sq = fmaf(s, s, sq);
        }
        #pragma unroll
        for (int off = CQ / 2; off > 0; off >>= 1)
            sq += __shfl_xor_sync(0xffffffffu, sq, off);
        float inv = 1.f / fmaxf(sqrtf(sq), 1e-12f);
        if (node < N_NODES) {
            #pragma unroll
            for (int jj = 0; jj < 4; jj++) {
                float o = v[jj] * inv;
                OUT[(size_t)node * NOUT + c + jj * CQ] = o;
                if (LAYER == 1)
                    g_h116[(size_t)node * 64 + c + jj * CQ] = __float2half_rn(o);
            }
        }
    }
}

// ---------------- scoring: one warp per batch element ----------------------
__global__ void __launch_bounds__(256) k_score(const float* __restrict__ uw,
                                               const float* __restrict__ ew,
                                               const int* __restrict__ uid,
                                               const int* __restrict__ pid,
                                               const int* __restrict__ nid,
                                               float* __restrict__ out) {
    int gidx = blockIdx.x * 256 + threadIdx.x;
    int b = gidx >> 5;
    int l = gidx & 31;
    if (b >= BATCH) return;
    int u  = uid[b];
    int pe = pid[b];
    int ne = nid[b];
    int p  = N_USERS + pe;
    int q  = N_USERS + ne;

    const float* fu = uw + (size_t)u * 64;
    const float* fp = ew + (size_t)pe * 64;
    const float* fq = ew + (size_t)ne * 64;

    float sp = 0.f, sn = 0.f;
    #pragma unroll
    for (int r = 0; r < 2; r++) {
        int cidx = l + r * 32;
        float a = fu[cidx];
        sp = fmaf(a, fp[cidx], sp);
        sn = fmaf(a, fq[cidx], sn);
    }
    #pragma unroll
    for (int r = 0; r < 2; r++) {
        int cidx = l + r * 32;
        float a = g_h1[(size_t)u * 64 + cidx];
        sp = fmaf(a, g_h1[(size_t)p * 64 + cidx], sp);
        sn = fmaf(a, g_h1[(size_t)q * 64 + cidx], sn);
    }
    {
        float a = g_h2[(size_t)u * 32 + l];
        sp = fmaf(a, g_h2[(size_t)p * 32 + l], sp);
        sn = fmaf(a, g_h2[(size_t)q * 32 + l], sn);
    }
    #pragma unroll
    for (int o = 16; o > 0; o >>= 1) {
        sp += __shfl_xor_sync(0xffffffffu, sp, o);
        sn += __shfl_xor_sync(0xffffffffu, sn, o);
    }
    if (l == 0) { out[b] = sp; out[BATCH + b] = sn; }
}

// ---------------- launch ---------------------------------------------------
extern "C" void kernel_launch(void* const* d_in, const int* in_sizes, int n_in,
                              void* d_out, int out_size) {
    const float* uw   = (const float*)d_in[0];
    const float* ew   = (const float*)d_in[1];
    const float* W1a  = (const float*)d_in[2];
    const float* b1a  = (const float*)d_in[3];
    const float* W2a  = (const float*)d_in[4];
    const float* b2a  = (const float*)d_in[5];
    const float* W1b  = (const float*)d_in[6];
    const float* b1b  = (const float*)d_in[7];
    const float* W2b  = (const float*)d_in[8];
    const float* b2b  = (const float*)d_in[9];
    const float* values   = (const float*)d_in[10];
    const int*   target   = (const int*)d_in[11];
    const int*   neighbor = (const int*)d_in[12];
    const int*   uid      = (const int*)d_in[13];
    const int*   pid      = (const int*)d_in[14];
    const int*   nid      = (const int*)d_in[15];
    float* out = (float*)d_out;

    // fp16 feature table + CSR build
    k_tofp16<<<(N_NODES * 64 / 8) / 256, 256>>>(uw, ew);
    k_zero_counts<<<(N_NODES / 4 + 255) / 256, 256>>>();
    k_count<<<N_EDGES / 256, 256>>>(target);
    k_scan1<<<SCAN_BLOCKS, 1024>>>();
    k_scan2<<<1, 256>>>();
    k_scan3<<<SCAN_BLOCKS, 1024>>>();
    k_scatter<<<N_EDGES / 256, 256>>>(target, neighbor, values);

    // Layer 1
    k_gather<1><<<N_NODES / 8, 256>>>();
    k_dense<1><<<N_NODES / 64, 256>>>(uw, ew, W1a, b1a, W2a, b2a);

    // Layer 2
    k_gather<2><<<N_NODES / 8, 256>>>();
    k_dense<2><<<(N_NODES + 127) / 128, 256>>>(uw, ew, W1b, b1b, W2b, b2b);

    // Scores
    k_score<<<(BATCH * 32) / 256, 256>>>(uw, ew, uid, pid, nid, out);
}

// round 8
// speedup vs baseline: 1.7935x; 1.1900x over previous
#include <cuda_runtime.h>
#include <cuda_fp16.h>
#include <mma.h>
#include <cstdint>

using namespace nvcuda;

#define N_USERS    50000
#define N_ENTITIES 150000
#define N_NODES    200000
#define N_EDGES    3200000
#define BATCH      4096
#define SCAN_BLOCKS 196            // 196*1024 = 200704 >= N_NODES

typedef unsigned long long ull;

// ---------------- scratch (device globals; no allocation allowed) ----------
__device__ __align__(16) float  g_hneigh[(size_t)N_NODES * 64];
__device__ __align__(16) float  g_h1[(size_t)N_NODES * 64];
__device__ __align__(16) float  g_h2[(size_t)N_NODES * 32];
__device__ __align__(16) __half g_feat16[(size_t)N_NODES * 64];  // fp16 ego features
__device__ __align__(16) __half g_h116[(size_t)N_NODES * 64];    // fp16 copy of h1
__device__ __align__(16) int    g_count[N_NODES];
__device__ __align__(16) int    g_rowstart[N_NODES + 4];
__device__ __align__(16) int    g_cursor[N_NODES + 4];
__device__ __align__(16) int    g_bsum[SCAN_BLOCKS];
__device__ __align__(16) int    g_boff[SCAN_BLOCKS];
__device__ __align__(16) int2   g_srt[N_EDGES];     // {neighbor, value-bits} sorted by target

__device__ __forceinline__ const float* feat0_row(const float* uw, const float* ew, int n) {
    return (n < N_USERS) ? (uw + (size_t)n * 64) : (ew + (size_t)(n - N_USERS) * 64);
}

// ---------------- fp16 feature table build ---------------------------------
__global__ void __launch_bounds__(256) k_tofp16(const float* __restrict__ uw,
                                                const float* __restrict__ ew) {
    size_t i = (size_t)blockIdx.x * 256 + threadIdx.x;
    size_t base = i * 8;
    int node = (int)(base >> 6);
    int col  = (int)(base & 63);
    const float* row = feat0_row(uw, ew, node);
    float4 a = *(const float4*)(row + col);
    float4 b = *(const float4*)(row + col + 4);
    __half2 h0 = __floats2half2_rn(a.x, a.y);
    __half2 h1 = __floats2half2_rn(a.z, a.w);
    __half2 h2 = __floats2half2_rn(b.x, b.y);
    __half2 h3 = __floats2half2_rn(b.z, b.w);
    uint4 out;
    out.x = *(const unsigned*)&h0;
    out.y = *(const unsigned*)&h1;
    out.z = *(const unsigned*)&h2;
    out.w = *(const unsigned*)&h3;
    *(uint4*)(g_feat16 + base) = out;
}

// ---------------- CSR build ------------------------------------------------
__global__ void __launch_bounds__(256) k_zero_counts() {
    int i = blockIdx.x * 256 + threadIdx.x;
    if (i < N_NODES / 4) ((int4*)g_count)[i] = make_int4(0, 0, 0, 0);
}

__global__ void __launch_bounds__(256) k_count(const int* __restrict__ target) {
    int e = blockIdx.x * 256 + threadIdx.x;           // grid exact: 3.2M/256
    atomicAdd(&g_count[__ldcs(target + e)], 1);
}

// Phase 1: per-block exclusive scan of 1024 counts.
__global__ void __launch_bounds__(1024) k_scan1() {
    __shared__ int warp_tot[32];
    int i = blockIdx.x * 1024 + threadIdx.x;
    int lane = threadIdx.x & 31, w = threadIdx.x >> 5;
    int v = (i < N_NODES) ? g_count[i] : 0;
    int x = v;
    #pragma unroll
    for (int o = 1; o < 32; o <<= 1) {
        int y = __shfl_up_sync(0xffffffffu, x, o);
        if (lane >= o) x += y;
    }
    if (lane == 31) warp_tot[w] = x;
    __syncthreads();
    if (w == 0) {
        int t = warp_tot[lane];
        #pragma unroll
        for (int o = 1; o < 32; o <<= 1) {
            int y = __shfl_up_sync(0xffffffffu, t, o);
            if (lane >= o) t += y;
        }
        warp_tot[lane] = t;
    }
    __syncthreads();
    int excl = x - v + ((w > 0) ? warp_tot[w - 1] : 0);
    if (i < N_NODES) g_rowstart[i] = excl;
    if (threadIdx.x == 1023) g_bsum[blockIdx.x] = excl + v;
}

// Phase 2: scan the 196 block totals.
__global__ void __launch_bounds__(256) k_scan2() {
    __shared__ int s[SCAN_BLOCKS];
    int t = threadIdx.x;
    if (t < SCAN_BLOCKS) s[t] = g_bsum[t];
    __syncthreads();
    if (t == 0) {
        int run = 0;
        for (int b = 0; b < SCAN_BLOCKS; b++) { int c = s[b]; s[b] = run; run += c; }
    }
    __syncthreads();
    if (t < SCAN_BLOCKS) g_boff[t] = s[t];
}

// Phase 3: add block offsets.
__global__ void __launch_bounds__(1024) k_scan3() {
    int i = blockIdx.x * 1024 + threadIdx.x;
    if (i < N_NODES) {
        int v = g_rowstart[i] + g_boff[blockIdx.x];
        g_rowstart[i] = v;
        g_cursor[i]   = v;
    }
    if (i == 0) g_rowstart[N_NODES] = N_EDGES;
}

__global__ void __launch_bounds__(256) k_scatter(const int* __restrict__ target,
                                                const int* __restrict__ neighbor,
                                                const float* __restrict__ values) {
    int e = blockIdx.x * 256 + threadIdx.x;           // grid exact
    int t = __ldcs(target + e);
    int2 rec = make_int2(__ldcs(neighbor + e), __float_as_int(__ldcs(values + e)));
    int pos = atomicAdd(&g_cursor[t], 1);
    __stcs((int2*)&g_srt[pos], rec);
}

// ---------------- CSR gather (fp16 rows): hneigh[n] = sum feat16[nb]*v -----
template <int LAYER>
__global__ void __launch_bounds__(256) k_gather() {
    int n = (blockIdx.x * 256 + threadIdx.x) >> 5;    // grid exact: 25000*8 warps
    int lane = threadIdx.x & 31;
    int c = lane & 15, half = lane >> 4;
    const __half* TAB = (LAYER == 1) ? g_feat16 : g_h116;
    int base = g_rowstart[n];
    int end  = g_rowstart[n + 1];
    float4 acc = make_float4(0.f, 0.f, 0.f, 0.f);
    for (int i = base + half; i < end; i += 2) {
        int2 e = __ldcs((const int2*)&g_srt[i]);
        float v = __int_as_float(e.y);
        uint2 hv = *(const uint2*)(TAB + (size_t)e.x * 64 + c * 4);
        float2 f01 = __half22float2(*(const __half2*)&hv.x);
        float2 f23 = __half22float2(*(const __half2*)&hv.y);
        acc.x = fmaf(f01.x, v, acc.x);
        acc.y = fmaf(f01.y, v, acc.y);
        acc.z = fmaf(f23.x, v, acc.z);
        acc.w = fmaf(f23.y, v, acc.w);
    }
    acc.x += __shfl_xor_sync(0xffffffffu, acc.x, 16);
    acc.y += __shfl_xor_sync(0xffffffffu, acc.y, 16);
    acc.z += __shfl_xor_sync(0xffffffffu, acc.z, 16);
    acc.w += __shfl_xor_sync(0xffffffffu, acc.w, 16);
    if (half == 0)
        __stcs((float4*)(g_hneigh + (size_t)n * 64 + c * 4), acc);
}

// ---------------- dense layers via wmma (fp16 x fp16 -> fp32) --------------
// Per block: 64 nodes. A = [s|p] (64 x 128) fp16 in shared (pitch 136 halves),
// B = [W1;W2] (128 x NOUT) fp16 (pitch BP halves). 8 warps cover the
// (4 m-tiles) x (NOUT/16 n-tiles) grid of m16n16k16 tiles, K = 8 steps.
// Accums staged to shared floats (aliasing A), then lrelu + row-l2norm.
template <int LAYER>
__global__ void __launch_bounds__(256) k_dense(const float* __restrict__ uw,
                                               const float* __restrict__ ew,
                                               const float* __restrict__ W1,
                                               const float* __restrict__ b1,
                                               const float* __restrict__ W2,
                                               const float* __restrict__ b2) {
    constexpr int NOUT = (LAYER == 1) ? 64 : 32;
    constexpr int AP   = 136;                  // A pitch (halves), 272B (16B mult)
    constexpr int BP   = (LAYER == 1) ? 72 : 40;   // B pitch (halves)
    constexpr int CP   = NOUT + 4;             // C pitch (floats): 68 / 36

    __shared__ __align__(16) char smem[64 * AP * 2 + 128 * BP * 2 + NOUT * 4];
    __half* Ah = (__half*)smem;                          // 64 x AP
    __half* Bh = (__half*)(smem + 64 * AP * 2);          // 128 x BP
    float*  bs = (float*) (smem + 64 * AP * 2 + 128 * BP * 2);
    float*  Cf = (float*)smem;                           // aliases Ah (64*CP*4 <= 64*AP*2)

    int tid  = threadIdx.x;
    int wid  = tid >> 5;
    int blockBase = blockIdx.x * 64;

    // ---- stage A: s,p from f,g (each float4 read once) --------------------
    for (int idx = tid; idx < 64 * 16; idx += 256) {
        int m  = idx >> 4;
        int q4 = idx & 15;
        int node = blockBase + m;
        const float* fr = (LAYER == 1) ? feat0_row(uw, ew, node)
                                       : (g_h1 + (size_t)node * 64);
        float4 fv = *(const float4*)(fr + q4 * 4);
        float4 gv = __ldcs((const float4*)(g_hneigh + (size_t)node * 64 + q4 * 4));
        __half* row = Ah + m * AP;
        *(__half2*)(row + q4 * 4)          = __floats2half2_rn(fv.x + gv.x, fv.y + gv.y);
        *(__half2*)(row + q4 * 4 + 2)      = __floats2half2_rn(fv.z + gv.z, fv.w + gv.w);
        *(__half2*)(row + 64 + q4 * 4)     = __floats2half2_rn(fv.x * gv.x, fv.y * gv.y);
        *(__half2*)(row + 64 + q4 * 4 + 2) = __floats2half2_rn(fv.z * gv.z, fv.w * gv.w);
    }
    // ---- stage B: [W1;W2] as fp16 -----------------------------------------
    for (int idx = tid; idx < 64 * NOUT; idx += 256) {   // half2 granularity
        int e = idx * 2;
        int k = e / NOUT;
        int j = e % NOUT;
        float2 w = (k < 64) ? *(const float2*)(W1 + k * NOUT + j)
                            : *(const float2*)(W2 + (k - 64) * NOUT + j);
        *(__half2*)(Bh + k * BP + j) = __floats2half2_rn(w.x, w.y);
    }
    if (tid < NOUT) bs[tid] = b1[tid] + b2[tid];
    __syncthreads();

    // ---- wmma mainloop ----------------------------------------------------
    constexpr int NT = NOUT / 16;             // n-tiles: 4 / 2
    constexpr int TPW = (4 * NT) / 8;         // tiles per warp: 2 / 1
    int mt = (TPW == 2) ? (wid >> 1) : (wid >> 1);
    int n0 = (TPW == 2) ? ((wid & 1) * 2) : (wid & 1);

    wmma::fragment<wmma::accumulator, 16, 16, 16, float> cfrag[TPW];
    #pragma unroll
    for (int t = 0; t < TPW; t++) wmma::fill_fragment(cfrag[t], 0.f);

    #pragma unroll
    for (int ks = 0; ks < 8; ks++) {
        wmma::fragment<wmma::matrix_a, 16, 16, 16, __half, wmma::row_major> afrag;
        wmma::load_matrix_sync(afrag, Ah + mt * 16 * AP + ks * 16, AP);
        #pragma unroll
        for (int t = 0; t < TPW; t++) {
            wmma::fragment<wmma::matrix_b, 16, 16, 16, __half, wmma::row_major> bfrag;
            wmma::load_matrix_sync(bfrag, Bh + ks * 16 * BP + (n0 + t) * 16, BP);
            wmma::mma_sync(cfrag[t], afrag, bfrag, cfrag[t]);
        }
    }
    __syncthreads();   // all reads of Ah done before aliased Cf writes
    #pragma unroll
    for (int t = 0; t < TPW; t++)
        wmma::store_matrix_sync(Cf + mt * 16 * CP + (n0 + t) * 16, cfrag[t], CP, wmma::mem_row_major);
    __syncthreads();

    // ---- epilogue: bias, lrelu, row l2-norm, store ------------------------
    constexpr int CPT = NOUT / 4;             // cols per thread: 16 / 8
    int m  = tid >> 2;
    int qd = tid & 3;
    int c0 = qd * CPT;
    float v[CPT];
    float sq = 0.f;
    #pragma unroll
    for (int j = 0; j < CPT; j++) {
        float s = Cf[m * CP + c0 + j] + bs[c0 + j];
        s = (s >= 0.f) ? s : 0.01f * s;
        v[j] = s;
        sq = fmaf(s, s, sq);
    }
    sq += __shfl_xor_sync(0xffffffffu, sq, 1);
    sq += __shfl_xor_sync(0xffffffffu, sq, 2);
    float inv = 1.f / fmaxf(sqrtf(sq), 1e-12f);
    int node = blockBase + m;
    float* OUT = (LAYER == 1) ? g_h1 : g_h2;
    #pragma unroll
    for (int j = 0; j < CPT; j++) {
        float o = v[j] * inv;
        OUT[(size_t)node * NOUT + c0 + j] = o;
        if (LAYER == 1)
            g_h116[(size_t)node * 64 + c0 + j] = __float2half_rn(o);
    }
}

// ---------------- scoring: one warp per batch element ----------------------
__global__ void __launch_bounds__(256) k_score(const float* __restrict__ uw,
                                               const float* __restrict__ ew,
                                               const int* __restrict__ uid,
                                               const int* __restrict__ pid,
                                               const int* __restrict__ nid,
                                               float* __restrict__ out) {
    int gidx = blockIdx.x * 256 + threadIdx.x;
    int b = gidx >> 5;
    int l = gidx & 31;
    if (b >= BATCH) return;
    int u  = uid[b];
    int pe = pid[b];
    int ne = nid[b];
    int p  = N_USERS + pe;
    int q  = N_USERS + ne;

    const float* fu = uw + (size_t)u * 64;
    const float* fp = ew + (size_t)pe * 64;
    const float* fq = ew + (size_t)ne * 64;

    float sp = 0.f, sn = 0.f;
    #pragma unroll
    for (int r = 0; r < 2; r++) {
        int cidx = l + r * 32;
        float a = fu[cidx];
        sp = fmaf(a, fp[cidx], sp);
        sn = fmaf(a, fq[cidx], sn);
    }
    #pragma unroll
    for (int r = 0; r < 2; r++) {
        int cidx = l + r * 32;
        float a = g_h1[(size_t)u * 64 + cidx];
        sp = fmaf(a, g_h1[(size_t)p * 64 + cidx], sp);
        sn = fmaf(a, g_h1[(size_t)q * 64 + cidx], sn);
    }
    {
        float a = g_h2[(size_t)u * 32 + l];
        sp = fmaf(a, g_h2[(size_t)p * 32 + l], sp);
        sn = fmaf(a, g_h2[(size_t)q * 32 + l], sn);
    }
    #pragma unroll
    for (int o = 16; o > 0; o >>= 1) {
        sp += __shfl_xor_sync(0xffffffffu, sp, o);
        sn += __shfl_xor_sync(0xffffffffu, sn, o);
    }
    if (l == 0) { out[b] = sp; out[BATCH + b] = sn; }
}

// ---------------- launch ---------------------------------------------------
extern "C" void kernel_launch(void* const* d_in, const int* in_sizes, int n_in,
                              void* d_out, int out_size) {
    const float* uw   = (const float*)d_in[0];
    const float* ew   = (const float*)d_in[1];
    const float* W1a  = (const float*)d_in[2];
    const float* b1a  = (const float*)d_in[3];
    const float* W2a  = (const float*)d_in[4];
    const float* b2a  = (const float*)d_in[5];
    const float* W1b  = (const float*)d_in[6];
    const float* b1b  = (const float*)d_in[7];
    const float* W2b  = (const float*)d_in[8];
    const float* b2b  = (const float*)d_in[9];
    const float* values   = (const float*)d_in[10];
    const int*   target   = (const int*)d_in[11];
    const int*   neighbor = (const int*)d_in[12];
    const int*   uid      = (const int*)d_in[13];
    const int*   pid      = (const int*)d_in[14];
    const int*   nid      = (const int*)d_in[15];
    float* out = (float*)d_out;

    // fp16 feature table + CSR build
    k_tofp16<<<(N_NODES * 64 / 8) / 256, 256>>>(uw, ew);
    k_zero_counts<<<(N_NODES / 4 + 255) / 256, 256>>>();
    k_count<<<N_EDGES / 256, 256>>>(target);
    k_scan1<<<SCAN_BLOCKS, 1024>>>();
    k_scan2<<<1, 256>>>();
    k_scan3<<<SCAN_BLOCKS, 1024>>>();
    k_scatter<<<N_EDGES / 256, 256>>>(target, neighbor, values);

    // Layer 1
    k_gather<1><<<N_NODES / 8, 256>>>();
    k_dense<1><<<N_NODES / 64, 256>>>(uw, ew, W1a, b1a, W2a, b2a);

    // Layer 2
    k_gather<2><<<N_NODES / 8, 256>>>();
    k_dense<2><<<N_NODES / 64, 256>>>(uw, ew, W1b, b1b, W2b, b2b);

    // Scores
    k_score<<<(BATCH * 32) / 256, 256>>>(uw, ew, uid, pid, nid, out);
}